// round 12
// baseline (speedup 1.0000x reference)
#include <cuda_runtime.h>
#include <math.h>
#include <stdint.h>

#define N 4096
#define D 512
#define F 512
#define NH 4
#define HD 128
#define NLAYER 2
#define EPS 1e-5f
#define NEG -1e9f
#define ATT_SCALE 0.08838834764831845f   // 1/sqrt(128)
#define CAP 512                          // max neighbors per row (mean ~42)

// ---------------- scratch (no allocation allowed -> device globals) --------
__device__ float g_x[N * D];
__device__ float g_h[N * D];
__device__ float g_q[N * D];
__device__ float g_k[N * D];
__device__ float g_v[N * D];
__device__ float g_o[N * D];
__device__ float g_mlp[N * F];
__device__ int g_nbidx[(size_t)N * CAP];   // 8MB neighbor lists
__device__ int g_nbcnt[N];
__device__ int g_mask_mode;   // 0 = uint8, 1 = int32, 2 = float32

// ---------------- helpers -----------------------------------------------------
__device__ __forceinline__ uint32_t smem_u32(const void* p) {
    uint32_t a;
    asm("{ .reg .u64 t; cvta.to.shared.u64 t, %1; cvt.u32.u64 %0, t; }"
        : "=r"(a) : "l"(p));
    return a;
}
__device__ __forceinline__ void cp16(uint32_t dst, const void* src) {
    asm volatile("cp.async.cg.shared.global [%0], [%1], 16;"
                 :: "r"(dst), "l"(src));
}
#define CP_COMMIT() asm volatile("cp.async.commit_group;" ::: "memory")
#define CP_WAIT0()  asm volatile("cp.async.wait_group 0;" ::: "memory")

__device__ __forceinline__ void mma16n8k8(float* c, const float* a,
                                          float b0, float b1)
{
    asm volatile(
        "mma.sync.aligned.m16n8k8.row.col.f32.tf32.tf32.f32 "
        "{%0,%1,%2,%3}, {%4,%5,%6,%7}, {%8,%9}, {%0,%1,%2,%3};\n"
        : "+f"(c[0]), "+f"(c[1]), "+f"(c[2]), "+f"(c[3])
        : "r"(__float_as_uint(a[0])), "r"(__float_as_uint(a[1])),
          "r"(__float_as_uint(a[2])), "r"(__float_as_uint(a[3])),
          "r"(__float_as_uint(b0)),   "r"(__float_as_uint(b1)));
}

// ---------------- mask dtype detection ---------------------------------------
__global__ void mask_detect_kernel(const unsigned int* __restrict__ raw)
{
    __shared__ int any_not01, any_notf;
    if (threadIdx.x == 0) { any_not01 = 0; any_notf = 0; }
    __syncthreads();
    int bad01 = 0, badf = 0;
    for (int i = threadIdx.x; i < 4096; i += blockDim.x) {
        unsigned int w = raw[i];
        if (w > 1u) bad01 = 1;
        if (w != 0u && w != 0x3F800000u) badf = 1;
    }
    if (bad01) atomicOr(&any_not01, 1);
    if (badf)  atomicOr(&any_notf, 1);
    __syncthreads();
    if (threadIdx.x == 0)
        g_mask_mode = (!any_not01) ? 1 : ((!any_notf) ? 2 : 0);
}

// ---------------- neighbor-list build (deterministic ordered compaction) -----
__global__ void __launch_bounds__(128) build_nb(const void* __restrict__ raw)
{
    const int row = blockIdx.x;
    const int t = threadIdx.x, w = t >> 5, lane = t & 31;
    __shared__ int warpcnt[4];
    __shared__ int cnt;
    if (t == 0) cnt = 0;
    const int mode = g_mask_mode;
    __syncthreads();

    for (int base = 0; base < N; base += 128) {
        int key = base + t;
        size_t idx = (size_t)row * N + key;
        int um;
        if (mode == 1)      um = ((const int*)raw)[idx] == 0;
        else if (mode == 2) um = ((const float*)raw)[idx] == 0.0f;
        else                um = ((const unsigned char*)raw)[idx] == 0;
        unsigned b = __ballot_sync(0xffffffffu, um);
        if (lane == 0) warpcnt[w] = __popc(b);
        __syncthreads();
        int basec = cnt;
        for (int ww = 0; ww < w; ww++) basec += warpcnt[ww];
        int pos = basec + __popc(b & ((1u << lane) - 1u));
        if (um && pos < CAP) g_nbidx[(size_t)row * CAP + pos] = key;
        __syncthreads();
        if (t == 0)
            cnt += warpcnt[0] + warpcnt[1] + warpcnt[2] + warpcnt[3];
        __syncthreads();
    }
    if (t == 0) g_nbcnt[row] = cnt < CAP ? cnt : CAP;
}

// ---------------- LayerNorm: one block (128 thr) per row ---------------------
__global__ void ln_kernel(const float* __restrict__ x, const float* __restrict__ g,
                          const float* __restrict__ b, float* __restrict__ out)
{
    int row = blockIdx.x;
    int t = threadIdx.x;
    float4 v = ((const float4*)(x + (size_t)row * D))[t];
    float s  = v.x + v.y + v.z + v.w;
    float ss = v.x * v.x + v.y * v.y + v.z * v.z + v.w * v.w;
    #pragma unroll
    for (int o = 16; o; o >>= 1) {
        s  += __shfl_xor_sync(0xffffffffu, s,  o);
        ss += __shfl_xor_sync(0xffffffffu, ss, o);
    }
    __shared__ float sh_s[4], sh_ss[4];
    int w = t >> 5;
    if ((t & 31) == 0) { sh_s[w] = s; sh_ss[w] = ss; }
    __syncthreads();
    s  = sh_s[0] + sh_s[1] + sh_s[2] + sh_s[3];
    ss = sh_ss[0] + sh_ss[1] + sh_ss[2] + sh_ss[3];
    float mu  = s * (1.0f / D);
    float var = ss * (1.0f / D) - mu * mu;
    float rs  = rsqrtf(var + EPS);
    float4 gv = ((const float4*)g)[t];
    float4 bv = ((const float4*)b)[t];
    float4 ov;
    ov.x = (v.x - mu) * rs * gv.x + bv.x;
    ov.y = (v.y - mu) * rs * gv.y + bv.y;
    ov.z = (v.z - mu) * rs * gv.z + bv.z;
    ov.w = (v.w - mu) * rs * gv.w + bv.w;
    ((float4*)(out + (size_t)row * D))[t] = ov;
}

// ---------------- tf32 mma.sync GEMM, cp.async double-buffered ---------------
// block: 128 thr / 4 warps (2m x 2n); tile BM=64 x BN=128 x BK=32.
#define GBM 64
#define GBN 128
#define GBK 32
#define GAP 36
#define STAGE_F ((GBM + GBN) * GAP)           // floats per stage
#define SMEM_GEMM (2 * STAGE_F * 4)           // 55296 bytes

__device__ __forceinline__ float gelu_exact(float v)
{
    return 0.5f * v * (1.0f + erff(v * 0.7071067811865475f));
}

template<bool GELU_ACT, bool RES>
__device__ __forceinline__ void gemm_body(
    const float* __restrict__ A, const float* __restrict__ W,
    const float* __restrict__ bias, const float* __restrict__ res,
    float* __restrict__ C, int K, int Nout, int bm, int bn, float* sm)
{
    const int t = threadIdx.x, w = t >> 5, lane = t & 31;
    const int g = lane >> 2, tg = lane & 3;
    const int wm = w & 1, wn = w >> 1;      // 2 m-warps x 2 n-warps

    float acc[2][8][4];
    #pragma unroll
    for (int mt = 0; mt < 2; mt++)
        #pragma unroll
        for (int nt = 0; nt < 8; nt++)
            acc[mt][nt][0] = acc[mt][nt][1] = acc[mt][nt][2] = acc[mt][nt][3] = 0.f;

    const int lr = t >> 3;            // loader row 0..15 (stride 16)
    const int lc = (t & 7) * 4;       // loader col (float4)
    const uint32_t sBase = smem_u32(sm);
    const uint32_t aDst = sBase + 4 * (lr * GAP + lc);
    const uint32_t wDst = aDst + 4 * (GBM * GAP);
    const float* Ap = A + (size_t)(bm + lr) * K + lc;
    const float* Wp = W + (size_t)(bn + lr) * K + lc;

    // prologue: stage 0
    #pragma unroll
    for (int i = 0; i < 4; i++)
        cp16(aDst + 4 * (16 * i) * GAP, Ap + (size_t)(16 * i) * K);
    #pragma unroll
    for (int i = 0; i < 8; i++)
        cp16(wDst + 4 * (16 * i) * GAP, Wp + (size_t)(16 * i) * K);
    CP_COMMIT();

    const int nchunks = K / GBK;
    for (int ch = 0; ch < nchunks; ch++) {
        CP_WAIT0();
        __syncthreads();
        if (ch + 1 < nchunks) {
            const uint32_t stOff = 4 * STAGE_F * ((ch + 1) & 1);
            const int kc = (ch + 1) * GBK;
            #pragma unroll
            for (int i = 0; i < 4; i++)
                cp16(aDst + stOff + 4 * (16 * i) * GAP, Ap + (size_t)(16 * i) * K + kc);
            #pragma unroll
            for (int i = 0; i < 8; i++)
                cp16(wDst + stOff + 4 * (16 * i) * GAP, Wp + (size_t)(16 * i) * K + kc);
            CP_COMMIT();
        }
        const float* As = sm + STAGE_F * (ch & 1);
        const float* Ws = As + GBM * GAP;

        #pragma unroll
        for (int ks = 0; ks < 4; ks++) {
            float a[2][4];
            #pragma unroll
            for (int mt = 0; mt < 2; mt++) {
                int r = wm * 32 + mt * 16 + g;
                a[mt][0] = As[r * GAP + 8 * ks + tg];
                a[mt][1] = As[(r + 8) * GAP + 8 * ks + tg];
                a[mt][2] = As[r * GAP + 8 * ks + tg + 4];
                a[mt][3] = As[(r + 8) * GAP + 8 * ks + tg + 4];
            }
            #pragma unroll
            for (int nt = 0; nt < 8; nt++) {
                int cr = wn * 64 + nt * 8 + g;
                float b0 = Ws[cr * GAP + 8 * ks + tg];
                float b1 = Ws[cr * GAP + 8 * ks + tg + 4];
                mma16n8k8(acc[0][nt], a[0], b0, b1);
                mma16n8k8(acc[1][nt], a[1], b0, b1);
            }
        }
    }

    #pragma unroll
    for (int mt = 0; mt < 2; mt++) {
        int row0 = bm + wm * 32 + mt * 16 + g;
        #pragma unroll
        for (int nt = 0; nt < 8; nt++) {
            int col = bn + wn * 64 + nt * 8 + 2 * tg;
            float b0 = bias[col], b1 = bias[col + 1];
            float v0 = acc[mt][nt][0] + b0, v1 = acc[mt][nt][1] + b1;
            float v2 = acc[mt][nt][2] + b0, v3 = acc[mt][nt][3] + b1;
            if (GELU_ACT) {
                v0 = gelu_exact(v0); v1 = gelu_exact(v1);
                v2 = gelu_exact(v2); v3 = gelu_exact(v3);
            }
            if (RES) {
                float2 r0 = *(const float2*)&res[(size_t)row0 * Nout + col];
                float2 r1 = *(const float2*)&res[(size_t)(row0 + 8) * Nout + col];
                v0 += r0.x; v1 += r0.y; v2 += r1.x; v3 += r1.y;
            }
            *(float2*)&C[(size_t)row0 * Nout + col] = make_float2(v0, v1);
            *(float2*)&C[(size_t)(row0 + 8) * Nout + col] = make_float2(v2, v3);
        }
    }
}

template<bool GELU_ACT, bool RES>
__global__ void __launch_bounds__(128) gemm_mma(
    const float* __restrict__ A, const float* __restrict__ W,
    const float* __restrict__ bias, const float* __restrict__ res,
    float* __restrict__ C, int K, int Nout)
{
    extern __shared__ float sm[];
    gemm_body<GELU_ACT, RES>(A, W, bias, res, C, K, Nout,
                             blockIdx.y * GBM, blockIdx.x * GBN, sm);
}

// fused Q/K/V projection: one launch
__global__ void __launch_bounds__(128) gemm_qkv(
    const float* __restrict__ A,
    const float* __restrict__ Wq, const float* __restrict__ Wk,
    const float* __restrict__ Wv,
    const float* __restrict__ Bq, const float* __restrict__ Bk,
    const float* __restrict__ Bv,
    float* __restrict__ Cq, float* __restrict__ Ck, float* __restrict__ Cv)
{
    extern __shared__ float sm[];
    const int sel = blockIdx.x >> 2;          // 4 n-blocks per output
    const int bn  = (blockIdx.x & 3) * GBN;
    const float* W = (sel == 0) ? Wq : (sel == 1) ? Wk : Wv;
    const float* B = (sel == 0) ? Bq : (sel == 1) ? Bk : Bv;
    float*       C = (sel == 0) ? Cq : (sel == 1) ? Ck : Cv;
    gemm_body<false, false>(A, W, B, nullptr, C, D, D,
                            blockIdx.y * GBM, bn, sm);
}

// ---------------- sparse gather attention (exact fp32, proven R6) ------------
__global__ void __launch_bounds__(128) attn_sparse(
    const float* __restrict__ Q, const float* __restrict__ K,
    const float* __restrict__ V, float* __restrict__ O)
{
    const int row = blockIdx.x;
    const int t = threadIdx.x, w = t >> 5, lane = t & 31;

    __shared__ int   nbs[CAP];
    __shared__ float sc[NH][CAP];

    const int cnt = g_nbcnt[row];
    const int cnt4 = (cnt + 3) & ~3;
    for (int i = t; i < cnt4; i += 128)
        nbs[i] = (i < cnt) ? g_nbidx[(size_t)row * CAP + i] : 0;

    float4 q4 = *(const float4*)&Q[(size_t)row * D + 4 * t];
    q4.x *= ATT_SCALE; q4.y *= ATT_SCALE; q4.z *= ATT_SCALE; q4.w *= ATT_SCALE;
    __syncthreads();

    for (int j = 0; j < cnt4; j += 4) {
        float d[4];
        #pragma unroll
        for (int e = 0; e < 4; e++) {
            const float4 k4 = *(const float4*)&K[(size_t)nbs[j + e] * D + 4 * t];
            d[e] = q4.x * k4.x + q4.y * k4.y + q4.z * k4.z + q4.w * k4.w;
        }
        #pragma unroll
        for (int o = 16; o; o >>= 1) {
            d[0] += __shfl_xor_sync(0xffffffffu, d[0], o);
            d[1] += __shfl_xor_sync(0xffffffffu, d[1], o);
            d[2] += __shfl_xor_sync(0xffffffffu, d[2], o);
            d[3] += __shfl_xor_sync(0xffffffffu, d[3], o);
        }
        if (lane == 0) {
            float4 sv;
            sv.x = (j + 0 < cnt) ? d[0] : NEG;
            sv.y = (j + 1 < cnt) ? d[1] : NEG;
            sv.z = (j + 2 < cnt) ? d[2] : NEG;
            sv.w = (j + 3 < cnt) ? d[3] : NEG;
            *(float4*)&sc[w][j] = sv;
        }
    }
    __syncwarp();

    float m = -INFINITY;
    for (int j = lane; j < cnt4; j += 32) m = fmaxf(m, sc[w][j]);
    #pragma unroll
    for (int o = 16; o; o >>= 1) m = fmaxf(m, __shfl_xor_sync(0xffffffffu, m, o));
    float s = 0.f;
    for (int j = lane; j < cnt4; j += 32) {
        float p = __expf(sc[w][j] - m);
        sc[w][j] = p;
        s += p;
    }
    #pragma unroll
    for (int o = 16; o; o >>= 1) s += __shfl_xor_sync(0xffffffffu, s, o);
    const float li = 1.f / s;
    __syncwarp();

    float4 acc = make_float4(0.f, 0.f, 0.f, 0.f);
    for (int j = 0; j < cnt4; j += 2) {
        float p0 = sc[w][j], p1 = sc[w][j + 1];
        float4 v0 = *(const float4*)&V[(size_t)nbs[j] * D + 4 * t];
        float4 v1 = *(const float4*)&V[(size_t)nbs[j + 1] * D + 4 * t];
        acc.x += p0 * v0.x + p1 * v1.x;
        acc.y += p0 * v0.y + p1 * v1.y;
        acc.z += p0 * v0.z + p1 * v1.z;
        acc.w += p0 * v0.w + p1 * v1.w;
    }
    acc.x *= li; acc.y *= li; acc.z *= li; acc.w *= li;
    *(float4*)&O[(size_t)row * D + 4 * t] = acc;
}

// ---------------- driver ------------------------------------------------------
extern "C" void kernel_launch(void* const* d_in, const int* in_sizes, int n_in,
                              void* d_out, int out_size)
{
    const float* nfeat = (const float*)d_in[0];
    const void*  maskraw = (const void*)d_in[1];
    const float* ln1_g = (const float*)d_in[2];
    const float* ln1_b = (const float*)d_in[3];
    const float* wq = (const float*)d_in[4];
    const float* bq = (const float*)d_in[5];
    const float* wk = (const float*)d_in[6];
    const float* bk = (const float*)d_in[7];
    const float* wv = (const float*)d_in[8];
    const float* bv = (const float*)d_in[9];
    const float* wo = (const float*)d_in[10];
    const float* bo = (const float*)d_in[11];
    const float* ln2_g = (const float*)d_in[12];
    const float* ln2_b = (const float*)d_in[13];
    const float* fc1_w = (const float*)d_in[14];
    const float* fc1_b = (const float*)d_in[15];
    const float* fc2_w = (const float*)d_in[16];
    const float* fc2_b = (const float*)d_in[17];

    float *x, *h, *q, *k, *v, *o, *mm;
    cudaGetSymbolAddress((void**)&x,  g_x);
    cudaGetSymbolAddress((void**)&h,  g_h);
    cudaGetSymbolAddress((void**)&q,  g_q);
    cudaGetSymbolAddress((void**)&k,  g_k);
    cudaGetSymbolAddress((void**)&v,  g_v);
    cudaGetSymbolAddress((void**)&o,  g_o);
    cudaGetSymbolAddress((void**)&mm, g_mlp);

    cudaFuncSetAttribute(gemm_qkv,
        cudaFuncAttributeMaxDynamicSharedMemorySize, SMEM_GEMM);
    cudaFuncSetAttribute(gemm_mma<false, true>,
        cudaFuncAttributeMaxDynamicSharedMemorySize, SMEM_GEMM);
    cudaFuncSetAttribute(gemm_mma<true, false>,
        cudaFuncAttributeMaxDynamicSharedMemorySize, SMEM_GEMM);

    mask_detect_kernel<<<1, 256>>>((const unsigned int*)maskraw);
    build_nb<<<N, 128>>>(maskraw);
    cudaMemcpyAsync(x, nfeat, (size_t)N * D * sizeof(float), cudaMemcpyDeviceToDevice);

    dim3 gemmGridD(D / GBN, N / GBM);      // (4, 64) = 256 blocks
    dim3 gemmGridF(F / GBN, N / GBM);
    dim3 qkvGrid(3 * D / GBN, N / GBM);    // (12, 64) = 768 blocks

    for (int l = 0; l < NLAYER; l++) {
        ln_kernel<<<N, 128>>>(x, ln1_g + l * D, ln1_b + l * D, h);
        gemm_qkv<<<qkvGrid, 128, SMEM_GEMM>>>(h,
            wq + (size_t)l * D * D, wk + (size_t)l * D * D, wv + (size_t)l * D * D,
            bq + l * D, bk + l * D, bv + l * D, q, k, v);
        attn_sparse<<<N, 128>>>(q, k, v, o);
        gemm_mma<false, true><<<gemmGridD, 128, SMEM_GEMM>>>(o, wo + (size_t)l * D * D, bo + l * D, x, x, D, D);
        ln_kernel<<<N, 128>>>(x, ln2_g + l * D, ln2_b + l * D, h);
        gemm_mma<true, false><<<gemmGridF, 128, SMEM_GEMM>>>(h, fc1_w + (size_t)l * F * D, fc1_b + l * F, nullptr, mm, D, F);
        float* outp = (l == NLAYER - 1) ? (float*)d_out : x;
        gemm_mma<false, true><<<gemmGridD, 128, SMEM_GEMM>>>(mm, fc2_w + (size_t)l * D * F, fc2_b + l * D, x, outp, F, D);
    }
}

// round 16
// speedup vs baseline: 1.0257x; 1.0257x over previous
#include <cuda_runtime.h>
#include <math.h>
#include <stdint.h>

#define N 4096
#define D 512
#define F 512
#define NH 4
#define HD 128
#define NLAYER 2
#define EPS 1e-5f
#define NEG -1e9f
#define ATT_SCALE 0.08838834764831845f   // 1/sqrt(128)
#define CAP 512                          // max neighbors per row (mean ~42)

// ---------------- scratch (no allocation allowed -> device globals) --------
__device__ float g_x[N * D];
__device__ float g_h[N * D];
__device__ float g_q[N * D];
__device__ float g_k[N * D];
__device__ float g_v[N * D];
__device__ float g_o[N * D];
__device__ float g_mlp[N * F];
__device__ int g_nbidx[(size_t)N * CAP];   // 8MB neighbor lists
__device__ int g_nbcnt[N];
__device__ int g_mask_mode;   // 0 = uint8, 1 = int32, 2 = float32

// ---------------- common mma helper (validated R4-R9) ------------------------
__device__ __forceinline__ void mma16n8k8(float* c, const float* a,
                                          float b0, float b1)
{
    asm volatile(
        "mma.sync.aligned.m16n8k8.row.col.f32.tf32.tf32.f32 "
        "{%0,%1,%2,%3}, {%4,%5,%6,%7}, {%8,%9}, {%0,%1,%2,%3};\n"
        : "+f"(c[0]), "+f"(c[1]), "+f"(c[2]), "+f"(c[3])
        : "r"(__float_as_uint(a[0])), "r"(__float_as_uint(a[1])),
          "r"(__float_as_uint(a[2])), "r"(__float_as_uint(a[3])),
          "r"(__float_as_uint(b0)),   "r"(__float_as_uint(b1)));
}

// ---------------- mask dtype detection ---------------------------------------
__global__ void mask_detect_kernel(const unsigned int* __restrict__ raw)
{
    __shared__ int any_not01, any_notf;
    if (threadIdx.x == 0) { any_not01 = 0; any_notf = 0; }
    __syncthreads();
    int bad01 = 0, badf = 0;
    for (int i = threadIdx.x; i < 4096; i += blockDim.x) {
        unsigned int w = raw[i];
        if (w > 1u) bad01 = 1;
        if (w != 0u && w != 0x3F800000u) badf = 1;
    }
    if (bad01) atomicOr(&any_not01, 1);
    if (badf)  atomicOr(&any_notf, 1);
    __syncthreads();
    if (threadIdx.x == 0)
        g_mask_mode = (!any_not01) ? 1 : ((!any_notf) ? 2 : 0);
}

// ---------------- neighbor-list build (deterministic ordered compaction) -----
__global__ void __launch_bounds__(128) build_nb(const void* __restrict__ raw)
{
    const int row = blockIdx.x;
    const int t = threadIdx.x, w = t >> 5, lane = t & 31;
    __shared__ int warpcnt[4];
    __shared__ int cnt;
    if (t == 0) cnt = 0;
    const int mode = g_mask_mode;
    __syncthreads();

    for (int base = 0; base < N; base += 128) {
        int key = base + t;
        size_t idx = (size_t)row * N + key;
        int um;
        if (mode == 1)      um = ((const int*)raw)[idx] == 0;
        else if (mode == 2) um = ((const float*)raw)[idx] == 0.0f;
        else                um = ((const unsigned char*)raw)[idx] == 0;
        unsigned b = __ballot_sync(0xffffffffu, um);
        if (lane == 0) warpcnt[w] = __popc(b);
        __syncthreads();
        int basec = cnt;
        for (int ww = 0; ww < w; ww++) basec += warpcnt[ww];
        int pos = basec + __popc(b & ((1u << lane) - 1u));
        if (um && pos < CAP) g_nbidx[(size_t)row * CAP + pos] = key;
        __syncthreads();
        if (t == 0)
            cnt += warpcnt[0] + warpcnt[1] + warpcnt[2] + warpcnt[3];
        __syncthreads();
    }
    if (t == 0) g_nbcnt[row] = cnt < CAP ? cnt : CAP;
}

// ---------------- LayerNorm: one block (128 thr) per row ---------------------
__global__ void ln_kernel(const float* __restrict__ x, const float* __restrict__ g,
                          const float* __restrict__ b, float* __restrict__ out)
{
    int row = blockIdx.x;
    int t = threadIdx.x;
    float4 v = ((const float4*)(x + (size_t)row * D))[t];
    float s  = v.x + v.y + v.z + v.w;
    float ss = v.x * v.x + v.y * v.y + v.z * v.z + v.w * v.w;
    #pragma unroll
    for (int o = 16; o; o >>= 1) {
        s  += __shfl_xor_sync(0xffffffffu, s,  o);
        ss += __shfl_xor_sync(0xffffffffu, ss, o);
    }
    __shared__ float sh_s[4], sh_ss[4];
    int w = t >> 5;
    if ((t & 31) == 0) { sh_s[w] = s; sh_ss[w] = ss; }
    __syncthreads();
    s  = sh_s[0] + sh_s[1] + sh_s[2] + sh_s[3];
    ss = sh_ss[0] + sh_ss[1] + sh_ss[2] + sh_ss[3];
    float mu  = s * (1.0f / D);
    float var = ss * (1.0f / D) - mu * mu;
    float rs  = rsqrtf(var + EPS);
    float4 gv = ((const float4*)g)[t];
    float4 bv = ((const float4*)b)[t];
    float4 ov;
    ov.x = (v.x - mu) * rs * gv.x + bv.x;
    ov.y = (v.y - mu) * rs * gv.y + bv.y;
    ov.z = (v.z - mu) * rs * gv.z + bv.z;
    ov.w = (v.w - mu) * rs * gv.w + bv.w;
    ((float4*)(out + (size_t)row * D))[t] = ov;
}

// ---------------- tf32 mma.sync GEMM: 32x64 warp tile, 2-stage smem ---------
// block: 128 thr / 4 warps (2m x 2n); tile BM=64 x BN=128 x BK=32.
// LDG->reg->STS path (R9, proven); two smem stages -> ONE sync per chunk.
#define GBM 64
#define GBN 128
#define GBK 32
#define GAP 36   // smem pitch: frag banks (row*36+tg) mod 32 = 4g+tg, unique
#define STAGE_F ((GBM + GBN) * GAP)           // floats per stage
#define SMEM_GEMM (2 * STAGE_F * 4)           // 55296 bytes

__device__ __forceinline__ float gelu_exact(float v)
{
    return 0.5f * v * (1.0f + erff(v * 0.7071067811865475f));
}

template<bool GELU_ACT, bool RES>
__device__ __forceinline__ void gemm_body(
    const float* __restrict__ A, const float* __restrict__ W,
    const float* __restrict__ bias, const float* __restrict__ res,
    float* __restrict__ C, int K, int Nout, int bm, int bn, float* sm)
{
    const int t = threadIdx.x, w = t >> 5, lane = t & 31;
    const int g = lane >> 2, tg = lane & 3;
    const int wm = w & 1, wn = w >> 1;      // 2 m-warps x 2 n-warps

    float acc[2][8][4];
    #pragma unroll
    for (int mt = 0; mt < 2; mt++)
        #pragma unroll
        for (int nt = 0; nt < 8; nt++)
            acc[mt][nt][0] = acc[mt][nt][1] = acc[mt][nt][2] = acc[mt][nt][3] = 0.f;

    const int lr = t >> 3;            // loader row 0..15 (stride 16)
    const int lc = (t & 7) * 4;       // loader col (float4)
    const float* Ap = A + (size_t)(bm + lr) * K + lc;
    const float* Wp = W + (size_t)(bn + lr) * K + lc;

    float4 pa[4], pw[8];
    // prologue: chunk 0 -> regs -> stage 0
    #pragma unroll
    for (int i = 0; i < 4; i++)
        pa[i] = *(const float4*)(Ap + (size_t)(16 * i) * K);
    #pragma unroll
    for (int i = 0; i < 8; i++)
        pw[i] = *(const float4*)(Wp + (size_t)(16 * i) * K);
    {
        float* As = sm;
        float* Ws = sm + GBM * GAP;
        #pragma unroll
        for (int i = 0; i < 4; i++)
            *(float4*)&As[(lr + 16 * i) * GAP + lc] = pa[i];
        #pragma unroll
        for (int i = 0; i < 8; i++)
            *(float4*)&Ws[(lr + 16 * i) * GAP + lc] = pw[i];
    }
    __syncthreads();

    const int nchunks = K / GBK;
    for (int ch = 0; ch < nchunks; ch++) {
        // issue next chunk's global loads early (latency hidden under mma)
        if (ch + 1 < nchunks) {
            const int kc = (ch + 1) * GBK;
            #pragma unroll
            for (int i = 0; i < 4; i++)
                pa[i] = *(const float4*)(Ap + (size_t)(16 * i) * K + kc);
            #pragma unroll
            for (int i = 0; i < 8; i++)
                pw[i] = *(const float4*)(Wp + (size_t)(16 * i) * K + kc);
        }

        const float* As = sm + STAGE_F * (ch & 1);
        const float* Ws = As + GBM * GAP;
        #pragma unroll
        for (int ks = 0; ks < 4; ks++) {
            float a[2][4];
            #pragma unroll
            for (int mt = 0; mt < 2; mt++) {
                int r = wm * 32 + mt * 16 + g;
                a[mt][0] = As[r * GAP + 8 * ks + tg];
                a[mt][1] = As[(r + 8) * GAP + 8 * ks + tg];
                a[mt][2] = As[r * GAP + 8 * ks + tg + 4];
                a[mt][3] = As[(r + 8) * GAP + 8 * ks + tg + 4];
            }
            #pragma unroll
            for (int nt = 0; nt < 8; nt++) {
                int cr = wn * 64 + nt * 8 + g;
                float b0 = Ws[cr * GAP + 8 * ks + tg];
                float b1 = Ws[cr * GAP + 8 * ks + tg + 4];
                mma16n8k8(acc[0][nt], a[0], b0, b1);
                mma16n8k8(acc[1][nt], a[1], b0, b1);
            }
        }

        // stage next chunk into the other buffer; single barrier per chunk
        if (ch + 1 < nchunks) {
            float* Asw = sm + STAGE_F * ((ch + 1) & 1);
            float* Wsw = Asw + GBM * GAP;
            #pragma unroll
            for (int i = 0; i < 4; i++)
                *(float4*)&Asw[(lr + 16 * i) * GAP + lc] = pa[i];
            #pragma unroll
            for (int i = 0; i < 8; i++)
                *(float4*)&Wsw[(lr + 16 * i) * GAP + lc] = pw[i];
            __syncthreads();
        }
    }

    #pragma unroll
    for (int mt = 0; mt < 2; mt++) {
        int row0 = bm + wm * 32 + mt * 16 + g;
        #pragma unroll
        for (int nt = 0; nt < 8; nt++) {
            int col = bn + wn * 64 + nt * 8 + 2 * tg;
            float b0 = bias[col], b1 = bias[col + 1];
            float v0 = acc[mt][nt][0] + b0, v1 = acc[mt][nt][1] + b1;
            float v2 = acc[mt][nt][2] + b0, v3 = acc[mt][nt][3] + b1;
            if (GELU_ACT) {
                v0 = gelu_exact(v0); v1 = gelu_exact(v1);
                v2 = gelu_exact(v2); v3 = gelu_exact(v3);
            }
            if (RES) {
                float2 r0 = *(const float2*)&res[(size_t)row0 * Nout + col];
                float2 r1 = *(const float2*)&res[(size_t)(row0 + 8) * Nout + col];
                v0 += r0.x; v1 += r0.y; v2 += r1.x; v3 += r1.y;
            }
            *(float2*)&C[(size_t)row0 * Nout + col] = make_float2(v0, v1);
            *(float2*)&C[(size_t)(row0 + 8) * Nout + col] = make_float2(v2, v3);
        }
    }
}

template<bool GELU_ACT, bool RES>
__global__ void __launch_bounds__(128) gemm_mma(
    const float* __restrict__ A, const float* __restrict__ W,
    const float* __restrict__ bias, const float* __restrict__ res,
    float* __restrict__ C, int K, int Nout)
{
    extern __shared__ float sm[];
    gemm_body<GELU_ACT, RES>(A, W, bias, res, C, K, Nout,
                             blockIdx.y * GBM, blockIdx.x * GBN, sm);
}

// fused Q/K/V projection: one launch
__global__ void __launch_bounds__(128) gemm_qkv(
    const float* __restrict__ A,
    const float* __restrict__ Wq, const float* __restrict__ Wk,
    const float* __restrict__ Wv,
    const float* __restrict__ Bq, const float* __restrict__ Bk,
    const float* __restrict__ Bv,
    float* __restrict__ Cq, float* __restrict__ Ck, float* __restrict__ Cv)
{
    extern __shared__ float sm[];
    const int sel = blockIdx.x >> 2;          // 4 n-blocks per output
    const int bn  = (blockIdx.x & 3) * GBN;
    const float* W = (sel == 0) ? Wq : (sel == 1) ? Wk : Wv;
    const float* B = (sel == 0) ? Bq : (sel == 1) ? Bk : Bv;
    float*       C = (sel == 0) ? Cq : (sel == 1) ? Ck : Cv;
    gemm_body<false, false>(A, W, B, nullptr, C, D, D,
                            blockIdx.y * GBM, bn, sm);
}

// ---------------- sparse gather attention (exact fp32, proven R6) ------------
__global__ void __launch_bounds__(128) attn_sparse(
    const float* __restrict__ Q, const float* __restrict__ K,
    const float* __restrict__ V, float* __restrict__ O)
{
    const int row = blockIdx.x;
    const int t = threadIdx.x, w = t >> 5, lane = t & 31;

    __shared__ int   nbs[CAP];
    __shared__ float sc[NH][CAP];

    const int cnt = g_nbcnt[row];
    const int cnt4 = (cnt + 3) & ~3;
    for (int i = t; i < cnt4; i += 128)
        nbs[i] = (i < cnt) ? g_nbidx[(size_t)row * CAP + i] : 0;

    float4 q4 = *(const float4*)&Q[(size_t)row * D + 4 * t];
    q4.x *= ATT_SCALE; q4.y *= ATT_SCALE; q4.z *= ATT_SCALE; q4.w *= ATT_SCALE;
    __syncthreads();

    for (int j = 0; j < cnt4; j += 4) {
        float d[4];
        #pragma unroll
        for (int e = 0; e < 4; e++) {
            const float4 k4 = *(const float4*)&K[(size_t)nbs[j + e] * D + 4 * t];
            d[e] = q4.x * k4.x + q4.y * k4.y + q4.z * k4.z + q4.w * k4.w;
        }
        #pragma unroll
        for (int o = 16; o; o >>= 1) {
            d[0] += __shfl_xor_sync(0xffffffffu, d[0], o);
            d[1] += __shfl_xor_sync(0xffffffffu, d[1], o);
            d[2] += __shfl_xor_sync(0xffffffffu, d[2], o);
            d[3] += __shfl_xor_sync(0xffffffffu, d[3], o);
        }
        if (lane == 0) {
            float4 sv;
            sv.x = (j + 0 < cnt) ? d[0] : NEG;
            sv.y = (j + 1 < cnt) ? d[1] : NEG;
            sv.z = (j + 2 < cnt) ? d[2] : NEG;
            sv.w = (j + 3 < cnt) ? d[3] : NEG;
            *(float4*)&sc[w][j] = sv;
        }
    }
    __syncwarp();

    float m = -INFINITY;
    for (int j = lane; j < cnt4; j += 32) m = fmaxf(m, sc[w][j]);
    #pragma unroll
    for (int o = 16; o; o >>= 1) m = fmaxf(m, __shfl_xor_sync(0xffffffffu, m, o));
    float s = 0.f;
    for (int j = lane; j < cnt4; j += 32) {
        float p = __expf(sc[w][j] - m);
        sc[w][j] = p;
        s += p;
    }
    #pragma unroll
    for (int o = 16; o; o >>= 1) s += __shfl_xor_sync(0xffffffffu, s, o);
    const float li = 1.f / s;
    __syncwarp();

    float4 acc = make_float4(0.f, 0.f, 0.f, 0.f);
    for (int j = 0; j < cnt4; j += 2) {
        float p0 = sc[w][j], p1 = sc[w][j + 1];
        float4 v0 = *(const float4*)&V[(size_t)nbs[j] * D + 4 * t];
        float4 v1 = *(const float4*)&V[(size_t)nbs[j + 1] * D + 4 * t];
        acc.x += p0 * v0.x + p1 * v1.x;
        acc.y += p0 * v0.y + p1 * v1.y;
        acc.z += p0 * v0.z + p1 * v1.z;
        acc.w += p0 * v0.w + p1 * v1.w;
    }
    acc.x *= li; acc.y *= li; acc.z *= li; acc.w *= li;
    *(float4*)&O[(size_t)row * D + 4 * t] = acc;
}

// ---------------- driver ------------------------------------------------------
extern "C" void kernel_launch(void* const* d_in, const int* in_sizes, int n_in,
                              void* d_out, int out_size)
{
    const float* nfeat = (const float*)d_in[0];
    const void*  maskraw = (const void*)d_in[1];
    const float* ln1_g = (const float*)d_in[2];
    const float* ln1_b = (const float*)d_in[3];
    const float* wq = (const float*)d_in[4];
    const float* bq = (const float*)d_in[5];
    const float* wk = (const float*)d_in[6];
    const float* bk = (const float*)d_in[7];
    const float* wv = (const float*)d_in[8];
    const float* bv = (const float*)d_in[9];
    const float* wo = (const float*)d_in[10];
    const float* bo = (const float*)d_in[11];
    const float* ln2_g = (const float*)d_in[12];
    const float* ln2_b = (const float*)d_in[13];
    const float* fc1_w = (const float*)d_in[14];
    const float* fc1_b = (const float*)d_in[15];
    const float* fc2_w = (const float*)d_in[16];
    const float* fc2_b = (const float*)d_in[17];

    float *x, *h, *q, *k, *v, *o, *mm;
    cudaGetSymbolAddress((void**)&x,  g_x);
    cudaGetSymbolAddress((void**)&h,  g_h);
    cudaGetSymbolAddress((void**)&q,  g_q);
    cudaGetSymbolAddress((void**)&k,  g_k);
    cudaGetSymbolAddress((void**)&v,  g_v);
    cudaGetSymbolAddress((void**)&o,  g_o);
    cudaGetSymbolAddress((void**)&mm, g_mlp);

    cudaFuncSetAttribute(gemm_qkv,
        cudaFuncAttributeMaxDynamicSharedMemorySize, SMEM_GEMM);
    cudaFuncSetAttribute(gemm_mma<false, true>,
        cudaFuncAttributeMaxDynamicSharedMemorySize, SMEM_GEMM);
    cudaFuncSetAttribute(gemm_mma<true, false>,
        cudaFuncAttributeMaxDynamicSharedMemorySize, SMEM_GEMM);

    mask_detect_kernel<<<1, 256>>>((const unsigned int*)maskraw);
    build_nb<<<N, 128>>>(maskraw);
    cudaMemcpyAsync(x, nfeat, (size_t)N * D * sizeof(float), cudaMemcpyDeviceToDevice);

    dim3 gemmGridD(D / GBN, N / GBM);      // (4, 64) = 256 blocks
    dim3 gemmGridF(F / GBN, N / GBM);
    dim3 qkvGrid(3 * D / GBN, N / GBM);    // (12, 64) = 768 blocks

    for (int l = 0; l < NLAYER; l++) {
        ln_kernel<<<N, 128>>>(x, ln1_g + l * D, ln1_b + l * D, h);
        gemm_qkv<<<qkvGrid, 128, SMEM_GEMM>>>(h,
            wq + (size_t)l * D * D, wk + (size_t)l * D * D, wv + (size_t)l * D * D,
            bq + l * D, bk + l * D, bv + l * D, q, k, v);
        attn_sparse<<<N, 128>>>(q, k, v, o);
        gemm_mma<false, true><<<gemmGridD, 128, SMEM_GEMM>>>(o, wo + (size_t)l * D * D, bo + l * D, x, x, D, D);
        ln_kernel<<<N, 128>>>(x, ln2_g + l * D, ln2_b + l * D, h);
        gemm_mma<true, false><<<gemmGridF, 128, SMEM_GEMM>>>(h, fc1_w + (size_t)l * F * D, fc1_b + l * F, nullptr, mm, D, F);
        float* outp = (l == NLAYER - 1) ? (float*)d_out : x;
        gemm_mma<false, true><<<gemmGridD, 128, SMEM_GEMM>>>(mm, fc2_w + (size_t)l * D * F, fc2_b + l * D, x, outp, F, D);
    }
}

// round 17
// speedup vs baseline: 1.1451x; 1.1164x over previous
#include <cuda_runtime.h>
#include <math.h>
#include <stdint.h>

#define N 4096
#define D 512
#define F 512
#define NH 4
#define HD 128
#define NLAYER 2
#define EPS 1e-5f
#define NEG -1e9f
#define ATT_SCALE 0.08838834764831845f   // 1/sqrt(128)
#define CAP 512                          // max neighbors per row (mean ~42)

// ---------------- scratch (no allocation allowed -> device globals) --------
__device__ float g_x[N * D];
__device__ float g_h[N * D];
__device__ float g_q[N * D];
__device__ float g_k[N * D];
__device__ float g_v[N * D];
__device__ float g_o[N * D];
__device__ float g_mlp[N * F];
__device__ int g_nbidx[(size_t)N * CAP];   // 8MB neighbor lists
__device__ int g_nbcnt[N];
__device__ int g_mask_mode;   // 0 = uint8, 1 = int32, 2 = float32

// ---------------- common mma helper (validated R4-R9) ------------------------
__device__ __forceinline__ void mma16n8k8(float* c, const float* a,
                                          float b0, float b1)
{
    asm volatile(
        "mma.sync.aligned.m16n8k8.row.col.f32.tf32.tf32.f32 "
        "{%0,%1,%2,%3}, {%4,%5,%6,%7}, {%8,%9}, {%0,%1,%2,%3};\n"
        : "+f"(c[0]), "+f"(c[1]), "+f"(c[2]), "+f"(c[3])
        : "r"(__float_as_uint(a[0])), "r"(__float_as_uint(a[1])),
          "r"(__float_as_uint(a[2])), "r"(__float_as_uint(a[3])),
          "r"(__float_as_uint(b0)),   "r"(__float_as_uint(b1)));
}

// ---------------- mask dtype detection ---------------------------------------
__global__ void mask_detect_kernel(const unsigned int* __restrict__ raw)
{
    __shared__ int any_not01, any_notf;
    if (threadIdx.x == 0) { any_not01 = 0; any_notf = 0; }
    __syncthreads();
    int bad01 = 0, badf = 0;
    for (int i = threadIdx.x; i < 4096; i += blockDim.x) {
        unsigned int w = raw[i];
        if (w > 1u) bad01 = 1;
        if (w != 0u && w != 0x3F800000u) badf = 1;
    }
    if (bad01) atomicOr(&any_not01, 1);
    if (badf)  atomicOr(&any_notf, 1);
    __syncthreads();
    if (threadIdx.x == 0)
        g_mask_mode = (!any_not01) ? 1 : ((!any_notf) ? 2 : 0);
}

// ---------------- neighbor-list build: one warp per row, barrier-free --------
__global__ void __launch_bounds__(256) build_nb(const void* __restrict__ raw)
{
    const int row = blockIdx.x * 8 + (threadIdx.x >> 5);   // 512 blocks x 8 warps
    const int lane = threadIdx.x & 31;
    const int mode = g_mask_mode;
    int* dst = g_nbidx + (size_t)row * CAP;

    int cnt = 0;
    for (int base = 0; base < N; base += 32) {
        const int key = base + lane;
        const size_t idx = (size_t)row * N + key;
        int um;   // unmasked?
        if (mode == 1)      um = ((const int*)raw)[idx] == 0;
        else if (mode == 2) um = ((const float*)raw)[idx] == 0.0f;
        else                um = ((const unsigned char*)raw)[idx] == 0;
        const unsigned b = __ballot_sync(0xffffffffu, um);
        const int pos = cnt + __popc(b & ((1u << lane) - 1u));
        if (um && pos < CAP) dst[pos] = key;
        cnt += __popc(b);
    }
    if (lane == 0) g_nbcnt[row] = cnt < CAP ? cnt : CAP;
}

// ---------------- LayerNorm: one block (128 thr) per row ---------------------
__global__ void ln_kernel(const float* __restrict__ x, const float* __restrict__ g,
                          const float* __restrict__ b, float* __restrict__ out)
{
    int row = blockIdx.x;
    int t = threadIdx.x;
    float4 v = ((const float4*)(x + (size_t)row * D))[t];
    float s  = v.x + v.y + v.z + v.w;
    float ss = v.x * v.x + v.y * v.y + v.z * v.z + v.w * v.w;
    #pragma unroll
    for (int o = 16; o; o >>= 1) {
        s  += __shfl_xor_sync(0xffffffffu, s,  o);
        ss += __shfl_xor_sync(0xffffffffu, ss, o);
    }
    __shared__ float sh_s[4], sh_ss[4];
    int w = t >> 5;
    if ((t & 31) == 0) { sh_s[w] = s; sh_ss[w] = ss; }
    __syncthreads();
    s  = sh_s[0] + sh_s[1] + sh_s[2] + sh_s[3];
    ss = sh_ss[0] + sh_ss[1] + sh_ss[2] + sh_ss[3];
    float mu  = s * (1.0f / D);
    float var = ss * (1.0f / D) - mu * mu;
    float rs  = rsqrtf(var + EPS);
    float4 gv = ((const float4*)g)[t];
    float4 bv = ((const float4*)b)[t];
    float4 ov;
    ov.x = (v.x - mu) * rs * gv.x + bv.x;
    ov.y = (v.y - mu) * rs * gv.y + bv.y;
    ov.z = (v.z - mu) * rs * gv.z + bv.z;
    ov.w = (v.w - mu) * rs * gv.w + bv.w;
    ((float4*)(out + (size_t)row * D))[t] = ov;
}

// ---------------- tf32 mma.sync GEMM (R9 exact: 32x64 warp tile) -------------
// block: 128 thr / 4 warps (2m x 2n); tile BM=64 x BN=128 x BK=32.
#define GBM 64
#define GBN 128
#define GBK 32
#define GAP 36   // smem pitch: frag banks (row*36+tg) mod 32 = 4g+tg, unique

__device__ __forceinline__ float gelu_exact(float v)
{
    return 0.5f * v * (1.0f + erff(v * 0.7071067811865475f));
}

template<bool GELU_ACT, bool RES>
__device__ __forceinline__ void gemm_body(
    const float* __restrict__ A, const float* __restrict__ W,
    const float* __restrict__ bias, const float* __restrict__ res,
    float* __restrict__ C, int K, int Nout, int bm, int bn,
    float* As, float* Ws)
{
    const int t = threadIdx.x, w = t >> 5, lane = t & 31;
    const int g = lane >> 2, tg = lane & 3;
    const int wm = w & 1, wn = w >> 1;      // 2 m-warps x 2 n-warps

    float acc[2][8][4];
    #pragma unroll
    for (int mt = 0; mt < 2; mt++)
        #pragma unroll
        for (int nt = 0; nt < 8; nt++)
            acc[mt][nt][0] = acc[mt][nt][1] = acc[mt][nt][2] = acc[mt][nt][3] = 0.f;

    const int lr = t >> 3;            // loader row 0..15 (stride 16)
    const int lc = (t & 7) * 4;       // loader col (float4)
    float4 pa[4], pw[8];
    #pragma unroll
    for (int i = 0; i < 4; i++)
        pa[i] = *(const float4*)&A[(size_t)(bm + lr + 16 * i) * K + lc];
    #pragma unroll
    for (int i = 0; i < 8; i++)
        pw[i] = *(const float4*)&W[(size_t)(bn + lr + 16 * i) * K + lc];

    const int nchunks = K / GBK;
    for (int ch = 0; ch < nchunks; ch++) {
        __syncthreads();
        #pragma unroll
        for (int i = 0; i < 4; i++)
            *(float4*)&As[(lr + 16 * i) * GAP + lc] = pa[i];
        #pragma unroll
        for (int i = 0; i < 8; i++)
            *(float4*)&Ws[(lr + 16 * i) * GAP + lc] = pw[i];
        if (ch + 1 < nchunks) {
            int kc = (ch + 1) * GBK;
            #pragma unroll
            for (int i = 0; i < 4; i++)
                pa[i] = *(const float4*)&A[(size_t)(bm + lr + 16 * i) * K + kc + lc];
            #pragma unroll
            for (int i = 0; i < 8; i++)
                pw[i] = *(const float4*)&W[(size_t)(bn + lr + 16 * i) * K + kc + lc];
        }
        __syncthreads();

        #pragma unroll
        for (int ks = 0; ks < 4; ks++) {
            float a[2][4];
            #pragma unroll
            for (int mt = 0; mt < 2; mt++) {
                int r = wm * 32 + mt * 16 + g;
                a[mt][0] = As[r * GAP + 8 * ks + tg];
                a[mt][1] = As[(r + 8) * GAP + 8 * ks + tg];
                a[mt][2] = As[r * GAP + 8 * ks + tg + 4];
                a[mt][3] = As[(r + 8) * GAP + 8 * ks + tg + 4];
            }
            #pragma unroll
            for (int nt = 0; nt < 8; nt++) {
                int cr = wn * 64 + nt * 8 + g;
                float b0 = Ws[cr * GAP + 8 * ks + tg];
                float b1 = Ws[cr * GAP + 8 * ks + tg + 4];
                mma16n8k8(acc[0][nt], a[0], b0, b1);
                mma16n8k8(acc[1][nt], a[1], b0, b1);
            }
        }
    }

    #pragma unroll
    for (int mt = 0; mt < 2; mt++) {
        int row0 = bm + wm * 32 + mt * 16 + g;
        #pragma unroll
        for (int nt = 0; nt < 8; nt++) {
            int col = bn + wn * 64 + nt * 8 + 2 * tg;
            float b0 = bias[col], b1 = bias[col + 1];
            float v0 = acc[mt][nt][0] + b0, v1 = acc[mt][nt][1] + b1;
            float v2 = acc[mt][nt][2] + b0, v3 = acc[mt][nt][3] + b1;
            if (GELU_ACT) {
                v0 = gelu_exact(v0); v1 = gelu_exact(v1);
                v2 = gelu_exact(v2); v3 = gelu_exact(v3);
            }
            if (RES) {
                float2 r0 = *(const float2*)&res[(size_t)row0 * Nout + col];
                float2 r1 = *(const float2*)&res[(size_t)(row0 + 8) * Nout + col];
                v0 += r0.x; v1 += r0.y; v2 += r1.x; v3 += r1.y;
            }
            *(float2*)&C[(size_t)row0 * Nout + col] = make_float2(v0, v1);
            *(float2*)&C[(size_t)(row0 + 8) * Nout + col] = make_float2(v2, v3);
        }
    }
}

template<bool GELU_ACT, bool RES>
__global__ void __launch_bounds__(128) gemm_mma(
    const float* __restrict__ A, const float* __restrict__ W,
    const float* __restrict__ bias, const float* __restrict__ res,
    float* __restrict__ C, int K, int Nout)
{
    __shared__ float As[GBM * GAP];   //  9KB
    __shared__ float Ws[GBN * GAP];   // 18KB
    gemm_body<GELU_ACT, RES>(A, W, bias, res, C, K, Nout,
                             blockIdx.y * GBM, blockIdx.x * GBN, As, Ws);
}

// fused Q/K/V projection: one launch
__global__ void __launch_bounds__(128) gemm_qkv(
    const float* __restrict__ A,
    const float* __restrict__ Wq, const float* __restrict__ Wk,
    const float* __restrict__ Wv,
    const float* __restrict__ Bq, const float* __restrict__ Bk,
    const float* __restrict__ Bv,
    float* __restrict__ Cq, float* __restrict__ Ck, float* __restrict__ Cv)
{
    __shared__ float As[GBM * GAP];
    __shared__ float Ws[GBN * GAP];
    const int sel = blockIdx.x >> 2;          // 4 n-blocks per output
    const int bn  = (blockIdx.x & 3) * GBN;
    const float* W = (sel == 0) ? Wq : (sel == 1) ? Wk : Wv;
    const float* B = (sel == 0) ? Bq : (sel == 1) ? Bk : Bv;
    float*       C = (sel == 0) ? Cq : (sel == 1) ? Ck : Cv;
    gemm_body<false, false>(A, W, B, nullptr, C, D, D,
                            blockIdx.y * GBM, bn, As, Ws);
}

// ---------------- sparse gather attention (exact fp32, proven R6) ------------
__global__ void __launch_bounds__(128) attn_sparse(
    const float* __restrict__ Q, const float* __restrict__ K,
    const float* __restrict__ V, float* __restrict__ O)
{
    const int row = blockIdx.x;
    const int t = threadIdx.x, w = t >> 5, lane = t & 31;

    __shared__ int   nbs[CAP];
    __shared__ float sc[NH][CAP];

    const int cnt = g_nbcnt[row];
    const int cnt4 = (cnt + 3) & ~3;
    for (int i = t; i < cnt4; i += 128)
        nbs[i] = (i < cnt) ? g_nbidx[(size_t)row * CAP + i] : 0;

    float4 q4 = *(const float4*)&Q[(size_t)row * D + 4 * t];
    q4.x *= ATT_SCALE; q4.y *= ATT_SCALE; q4.z *= ATT_SCALE; q4.w *= ATT_SCALE;
    __syncthreads();

    for (int j = 0; j < cnt4; j += 4) {
        float d[4];
        #pragma unroll
        for (int e = 0; e < 4; e++) {
            const float4 k4 = *(const float4*)&K[(size_t)nbs[j + e] * D + 4 * t];
            d[e] = q4.x * k4.x + q4.y * k4.y + q4.z * k4.z + q4.w * k4.w;
        }
        #pragma unroll
        for (int o = 16; o; o >>= 1) {
            d[0] += __shfl_xor_sync(0xffffffffu, d[0], o);
            d[1] += __shfl_xor_sync(0xffffffffu, d[1], o);
            d[2] += __shfl_xor_sync(0xffffffffu, d[2], o);
            d[3] += __shfl_xor_sync(0xffffffffu, d[3], o);
        }
        if (lane == 0) {
            float4 sv;
            sv.x = (j + 0 < cnt) ? d[0] : NEG;
            sv.y = (j + 1 < cnt) ? d[1] : NEG;
            sv.z = (j + 2 < cnt) ? d[2] : NEG;
            sv.w = (j + 3 < cnt) ? d[3] : NEG;
            *(float4*)&sc[w][j] = sv;
        }
    }
    __syncwarp();

    float m = -INFINITY;
    for (int j = lane; j < cnt4; j += 32) m = fmaxf(m, sc[w][j]);
    #pragma unroll
    for (int o = 16; o; o >>= 1) m = fmaxf(m, __shfl_xor_sync(0xffffffffu, m, o));
    float s = 0.f;
    for (int j = lane; j < cnt4; j += 32) {
        float p = __expf(sc[w][j] - m);
        sc[w][j] = p;
        s += p;
    }
    #pragma unroll
    for (int o = 16; o; o >>= 1) s += __shfl_xor_sync(0xffffffffu, s, o);
    const float li = 1.f / s;
    __syncwarp();

    float4 acc = make_float4(0.f, 0.f, 0.f, 0.f);
    for (int j = 0; j < cnt4; j += 2) {
        float p0 = sc[w][j], p1 = sc[w][j + 1];
        float4 v0 = *(const float4*)&V[(size_t)nbs[j] * D + 4 * t];
        float4 v1 = *(const float4*)&V[(size_t)nbs[j + 1] * D + 4 * t];
        acc.x += p0 * v0.x + p1 * v1.x;
        acc.y += p0 * v0.y + p1 * v1.y;
        acc.z += p0 * v0.z + p1 * v1.z;
        acc.w += p0 * v0.w + p1 * v1.w;
    }
    acc.x *= li; acc.y *= li; acc.z *= li; acc.w *= li;
    *(float4*)&O[(size_t)row * D + 4 * t] = acc;
}

// ---------------- driver ------------------------------------------------------
extern "C" void kernel_launch(void* const* d_in, const int* in_sizes, int n_in,
                              void* d_out, int out_size)
{
    const float* nfeat = (const float*)d_in[0];
    const void*  maskraw = (const void*)d_in[1];
    const float* ln1_g = (const float*)d_in[2];
    const float* ln1_b = (const float*)d_in[3];
    const float* wq = (const float*)d_in[4];
    const float* bq = (const float*)d_in[5];
    const float* wk = (const float*)d_in[6];
    const float* bk = (const float*)d_in[7];
    const float* wv = (const float*)d_in[8];
    const float* bv = (const float*)d_in[9];
    const float* wo = (const float*)d_in[10];
    const float* bo = (const float*)d_in[11];
    const float* ln2_g = (const float*)d_in[12];
    const float* ln2_b = (const float*)d_in[13];
    const float* fc1_w = (const float*)d_in[14];
    const float* fc1_b = (const float*)d_in[15];
    const float* fc2_w = (const float*)d_in[16];
    const float* fc2_b = (const float*)d_in[17];

    float *x, *h, *q, *k, *v, *o, *mm;
    cudaGetSymbolAddress((void**)&x,  g_x);
    cudaGetSymbolAddress((void**)&h,  g_h);
    cudaGetSymbolAddress((void**)&q,  g_q);
    cudaGetSymbolAddress((void**)&k,  g_k);
    cudaGetSymbolAddress((void**)&v,  g_v);
    cudaGetSymbolAddress((void**)&o,  g_o);
    cudaGetSymbolAddress((void**)&mm, g_mlp);

    mask_detect_kernel<<<1, 256>>>((const unsigned int*)maskraw);
    build_nb<<<N / 8, 256>>>(maskraw);

    dim3 gemmGridD(D / GBN, N / GBM);      // (4, 64) = 256 blocks
    dim3 gemmGridF(F / GBN, N / GBM);
    dim3 qkvGrid(3 * D / GBN, N / GBM);    // (12, 64) = 768 blocks

    for (int l = 0; l < NLAYER; l++) {
        // layer 0 reads the input tensor directly; no staging memcpy
        const float* xin = (l == 0) ? nfeat : x;
        ln_kernel<<<N, 128>>>(xin, ln1_g + l * D, ln1_b + l * D, h);
        gemm_qkv<<<qkvGrid, 128>>>(h,
            wq + (size_t)l * D * D, wk + (size_t)l * D * D, wv + (size_t)l * D * D,
            bq + l * D, bk + l * D, bv + l * D, q, k, v);
        attn_sparse<<<N, 128>>>(q, k, v, o);
        gemm_mma<false, true><<<gemmGridD, 128>>>(o, wo + (size_t)l * D * D, bo + l * D, xin, x, D, D);
        ln_kernel<<<N, 128>>>(x, ln2_g + l * D, ln2_b + l * D, h);
        gemm_mma<true, false><<<gemmGridF, 128>>>(h, fc1_w + (size_t)l * F * D, fc1_b + l * F, nullptr, mm, D, F);
        float* outp = (l == NLAYER - 1) ? (float*)d_out : x;
        gemm_mma<false, true><<<gemmGridD, 128>>>(mm, fc2_w + (size_t)l * D * F, fc2_b + l * D, x, outp, F, D);
    }
}